// round 1
// baseline (speedup 1.0000x reference)
#include <cuda_runtime.h>
#include <math.h>

#define Bc 2
#define Hc 16
#define Sc 2048
#define Dc 72

static constexpr int NROWS = Bc * Hc * Sc;   // 65536
static constexpr int KS_STRIDE = 73;
static constexpr int P_STRIDE  = 65;
static constexpr int QS_SZ = 64 * 72;
static constexpr int KS_SZ = 64 * KS_STRIDE;
static constexpr int VS_SZ = 64 * 72;
static constexpr int P_SZ  = 64 * P_STRIDE;
static constexpr int SMEM_FLOATS = QS_SZ + KS_SZ + VS_SZ + P_SZ;   // 18048 floats = 72192 B

__device__ __align__(16) float g_q[(size_t)NROWS * Dc];
__device__ __align__(16) float g_k[(size_t)NROWS * Dc];

// ---------------------------------------------------------------------------
// Zero the invalid query region (rows q < 576 for every (b,h)).
// 32 bh * 576 rows * 72 floats / 4 = 331776 float4 = 1296 blocks * 256 thr
// ---------------------------------------------------------------------------
__global__ void zero_kernel(float4* __restrict__ out) {
    int idx = blockIdx.x * 256 + threadIdx.x;            // < 331776
    int bh = idx / 10368;                                // 576*18 float4 per bh
    int r  = idx % 10368;
    out[(size_t)bh * (Sc * 18) + r] = make_float4(0.f, 0.f, 0.f, 0.f);
}

// ---------------------------------------------------------------------------
// Preprocess: theta + rotary + L2 norm for q and k. One warp per (b,h,s) row.
// ---------------------------------------------------------------------------
__global__ void prep_kernel(const float* __restrict__ q, const float* __restrict__ k,
                            const float* __restrict__ pos, const float* __restrict__ pos_orig,
                            const float* __restrict__ time_, const float* __restrict__ freqs,
                            const float* __restrict__ t_freqs, const float* __restrict__ scale) {
    int warp = threadIdx.x >> 5, lane = threadIdx.x & 31;
    int row = blockIdx.x * 8 + warp;                     // 0..65535
    int s  = row & (Sc - 1);
    int bh = row >> 11;
    int h  = bh & (Hc - 1);
    int b  = bh >> 4;

    const float* qr = q + (size_t)row * Dc;
    const float* kr = k + (size_t)row * Dc;

    __shared__ float sq[8][Dc], sk[8][Dc];
    for (int e = lane; e < Dc; e += 32) { sq[warp][e] = qr[e]; sk[warp][e] = kr[e]; }
    __syncwarp();

    int ps = (b * Sc + s) * 2;
    float px  = 2.f * pos[ps]       - 1.f;
    float py  = 2.f * pos[ps + 1]   - 1.f;
    float pxo = 2.f * pos_orig[ps]     - 1.f;
    float pyo = 2.f * pos_orig[ps + 1] - 1.f;
    float tm  = time_[b * Sc + s];

    float oq[3], ok[3];
    float ssq = 0.f, ssk = 0.f;
    #pragma unroll
    for (int slot = 0; slot < 3; slot++) {
        int j = lane + slot * 32;
        if (j < Dc) {
            float xq = sq[warp][j], xk = sk[warp][j];
            if (j < 60) {
                int jj = (j < 30) ? j : j - 30;
                int seg = jj / 6, i = jj % 6;
                float coef, fr;
                if      (seg == 0) { coef = pyo; fr = freqs[96 + h * 6 + i]; }
                else if (seg == 1) { coef = py;  fr = freqs[96 + h * 6 + i]; }
                else if (seg == 2) { coef = pxo; fr = freqs[h * 6 + i]; }
                else if (seg == 3) { coef = px;  fr = freqs[h * 6 + i]; }
                else               { coef = tm;  fr = t_freqs[h * 6 + i]; }
                float th = coef * fr, c, sn;
                sincosf(th, &sn, &c);
                if (j < 30) {
                    oq[slot] = xq * c - sq[warp][j + 30] * sn;
                    ok[slot] = xk * c - sk[warp][j + 30] * sn;
                } else {
                    oq[slot] = xq * c + sq[warp][j - 30] * sn;
                    ok[slot] = xk * c + sk[warp][j - 30] * sn;
                }
            } else { oq[slot] = xq; ok[slot] = xk; }
            ssq += oq[slot] * oq[slot];
            ssk += ok[slot] * ok[slot];
        } else { oq[slot] = 0.f; ok[slot] = 0.f; }
    }
    #pragma unroll
    for (int off = 16; off; off >>= 1) {
        ssq += __shfl_xor_sync(0xffffffffu, ssq, off);
        ssk += __shfl_xor_sync(0xffffffffu, ssk, off);
    }
    float ss = sqrtf(scale[h]);
    float rq = ss * rsqrtf(ssq + 1e-6f);
    float rk = ss * rsqrtf(ssk + 1e-6f);
    #pragma unroll
    for (int slot = 0; slot < 3; slot++) {
        int j = lane + slot * 32;
        if (j < Dc) {
            g_q[(size_t)row * Dc + j] = oq[slot] * rq;
            g_k[(size_t)row * Dc + j] = ok[slot] * rk;
        }
    }
}

// ---------------------------------------------------------------------------
// Attention. Scores bounded by 1.5 (normalized q,k) -> no softmax max needed.
// grid = (23 q-tiles of 64 rows starting at q=576, 32 bh), 256 threads.
//   m < 8  : causal region, 9+m full K-tiles + 1 diagonal-masked tile.
//   m >= 8 : dense region, 17 full K-tiles (k<1088) + self key k==q.
// ---------------------------------------------------------------------------
__global__ void __launch_bounds__(256, 2)
attn_kernel(const float* __restrict__ v, float* __restrict__ out) {
    extern __shared__ float sm[];
    float* Qs = sm;
    float* Ks = sm + QS_SZ;
    float* Vs = Ks + KS_SZ;
    float* P  = Vs + VS_SZ;

    int t  = threadIdx.x;
    int m  = blockIdx.x;
    int bh = blockIdx.y;
    int q0 = 576 + 64 * m;
    size_t base = (size_t)bh * Sc;

    {   // load Q tile (64x72, float4)
        const float4* src = (const float4*)(g_q + (base + q0) * Dc);
        float4* dst = (float4*)Qs;
        #pragma unroll
        for (int i = t; i < 64 * 18; i += 256) dst[i] = src[i];
    }

    bool causal = (m < 8);
    int nt = causal ? (10 + m) : 17;

    float acc[18];
    #pragma unroll
    for (int i = 0; i < 18; i++) acc[i] = 0.f;
    float l = 0.f;

    int qown = t >> 2, g = t & 3;
    int ty = t >> 4, tx = t & 15;

    for (int kt = 0; kt < nt; kt++) {
        __syncthreads();   // previous phase2 done with Vs/P
        {   // load K (padded scatter) and V (float4 direct)
            const float4* ksrc = (const float4*)(g_k + (base + (size_t)kt * 64) * Dc);
            const float4* vsrc = (const float4*)(v   + (base + (size_t)kt * 64) * Dc);
            float4* vdst = (float4*)Vs;
            for (int i = t; i < 64 * 18; i += 256) {
                float4 kv = ksrc[i];
                vdst[i] = vsrc[i];
                int r = i / 18, c = (i % 18) * 4;
                float* kd = Ks + r * KS_STRIDE + c;
                kd[0] = kv.x; kd[1] = kv.y; kd[2] = kv.z; kd[3] = kv.w;
            }
        }
        __syncthreads();

        // phase 1: 4x4 microtile QK^T
        float sc00=0.f,sc01=0.f,sc02=0.f,sc03=0.f;
        float sc10=0.f,sc11=0.f,sc12=0.f,sc13=0.f;
        float sc20=0.f,sc21=0.f,sc22=0.f,sc23=0.f;
        float sc30=0.f,sc31=0.f,sc32=0.f,sc33=0.f;
        const float* qb = Qs + (ty * 4) * Dc;
        const float* kb = Ks + (tx * 4) * KS_STRIDE;
        #pragma unroll 8
        for (int d = 0; d < Dc; d++) {
            float qa0 = qb[d], qa1 = qb[Dc + d], qa2 = qb[2 * Dc + d], qa3 = qb[3 * Dc + d];
            float ka0 = kb[d], ka1 = kb[KS_STRIDE + d], ka2 = kb[2 * KS_STRIDE + d], ka3 = kb[3 * KS_STRIDE + d];
            sc00 += qa0 * ka0; sc01 += qa0 * ka1; sc02 += qa0 * ka2; sc03 += qa0 * ka3;
            sc10 += qa1 * ka0; sc11 += qa1 * ka1; sc12 += qa1 * ka2; sc13 += qa1 * ka3;
            sc20 += qa2 * ka0; sc21 += qa2 * ka1; sc22 += qa2 * ka2; sc23 += qa2 * ka3;
            sc30 += qa3 * ka0; sc31 += qa3 * ka1; sc32 += qa3 * ka2; sc33 += qa3 * ka3;
        }
        bool masked = causal && (kt == nt - 1);
        float scs[4][4] = {{sc00,sc01,sc02,sc03},{sc10,sc11,sc12,sc13},
                           {sc20,sc21,sc22,sc23},{sc30,sc31,sc32,sc33}};
        #pragma unroll
        for (int i = 0; i < 4; i++) {
            #pragma unroll
            for (int j = 0; j < 4; j++) {
                float p = (masked && (tx * 4 + j > ty * 4 + i)) ? 0.f : __expf(scs[i][j]);
                P[(ty * 4 + i) * P_STRIDE + tx * 4 + j] = p;
            }
        }
        __syncthreads();

        // phase 2: O += P @ V, thread owns (qown, dims g*18..g*18+17)
        const float* Prow = P + qown * P_STRIDE;
        #pragma unroll 4
        for (int kk = 0; kk < 64; kk++) {
            float p = Prow[kk];
            l += p;
            const float2* vr = (const float2*)(Vs + kk * Dc + g * 18);
            #pragma unroll
            for (int i2 = 0; i2 < 9; i2++) {
                float2 vv = vr[i2];
                acc[2 * i2]     += p * vv.x;
                acc[2 * i2 + 1] += p * vv.y;
            }
        }
    }

    if (!causal) {   // self key k == q
        int qg = q0 + qown;
        const float* kr = g_k + (base + qg) * Dc + g * 18;
        const float* qrow = Qs + qown * Dc + g * 18;
        float sp = 0.f;
        #pragma unroll
        for (int i = 0; i < 18; i++) sp += qrow[i] * kr[i];
        sp += __shfl_xor_sync(0xffffffffu, sp, 1);
        sp += __shfl_xor_sync(0xffffffffu, sp, 2);
        float p = __expf(sp);
        l += p;
        const float* vr = v + (base + qg) * Dc + g * 18;
        #pragma unroll
        for (int i = 0; i < 18; i++) acc[i] += p * vr[i];
    }

    float inv = 1.f / l;
    float* orow = out + (base + q0 + qown) * Dc + g * 18;
    #pragma unroll
    for (int i = 0; i < 18; i++) orow[i] = acc[i] * inv;
}

// ---------------------------------------------------------------------------
extern "C" void kernel_launch(void* const* d_in, const int* in_sizes, int n_in,
                              void* d_out, int out_size) {
    const float* q        = (const float*)d_in[0];
    const float* k        = (const float*)d_in[1];
    const float* v        = (const float*)d_in[2];
    const float* pos      = (const float*)d_in[3];
    const float* pos_orig = (const float*)d_in[4];
    const float* time_    = (const float*)d_in[5];
    const float* freqs    = (const float*)d_in[6];
    const float* t_freqs  = (const float*)d_in[7];
    const float* scale    = (const float*)d_in[8];
    float* out = (float*)d_out;

    cudaFuncSetAttribute(attn_kernel, cudaFuncAttributeMaxDynamicSharedMemorySize,
                         SMEM_FLOATS * sizeof(float));

    zero_kernel<<<1296, 256>>>((float4*)out);
    prep_kernel<<<Bc * Hc * Sc / 8, 256>>>(q, k, pos, pos_orig, time_, freqs, t_freqs, scale);
    attn_kernel<<<dim3(23, 32), 256, SMEM_FLOATS * sizeof(float)>>>(v, out);
}